// round 6
// baseline (speedup 1.0000x reference)
#include <cuda_runtime.h>

// SWT (stationary wavelet transform), db4, 3 levels, wrap padding.
// x: (64,32,4096) f32 -> out: (64,32,4096,4) f32 = [a3, d3, d2, d1] per t.
//
// Per level (dil = 1,2,4):
//   out[t] = sum_{j=0..7} f[j] * in[(t + (4-j)*dil) & 4095]
// lo chain: x -> lo1 -> lo2 -> (a3); details d1 (from x), d2 (from lo1),
// d3 (from lo2).

#define SWT_T     4096
#define SWT_TMASK 4095
#define SWT_NT    512
#define SWT_EPT   (SWT_T / SWT_NT)   // 8 elements per thread

__global__ __launch_bounds__(SWT_NT)
void swt_db4_l3_kernel(const float* __restrict__ x,
                       const float* __restrict__ dec_lo,
                       const float* __restrict__ dec_hi,
                       float4* __restrict__ out)
{
    __shared__ float s_a[SWT_T];   // holds x, later lo2
    __shared__ float s_b[SWT_T];   // holds lo1

    const int row = blockIdx.x;                 // 0 .. 2047  (b*32+n)
    const int tid = threadIdx.x;

    // Filters into registers (L1-cached, 16 scalar loads per thread).
    float flo[8], fhi[8];
#pragma unroll
    for (int j = 0; j < 8; ++j) {
        flo[j] = __ldg(&dec_lo[j]);
        fhi[j] = __ldg(&dec_hi[j]);
    }

    // ---- Load row into SMEM (vectorized, coalesced) ----
    const float4* xr4 = reinterpret_cast<const float4*>(x + (size_t)row * SWT_T);
    float4* s_a4 = reinterpret_cast<float4*>(s_a);
#pragma unroll
    for (int i = 0; i < SWT_T / 4 / SWT_NT; ++i)      // 2 iterations
        s_a4[tid + i * SWT_NT] = xr4[tid + i * SWT_NT];
    __syncthreads();

    // ---- Level 1 (dil=1): lo1 -> s_b, d1 -> registers ----
    float d1[SWT_EPT];
#pragma unroll
    for (int r = 0; r < SWT_EPT; ++r) {
        const int t = tid + r * SWT_NT;
        float acc_lo = 0.f, acc_hi = 0.f;
#pragma unroll
        for (int j = 0; j < 8; ++j) {
            const float v = s_a[(t + (4 - j)) & SWT_TMASK];
            acc_lo = fmaf(flo[j], v, acc_lo);
            acc_hi = fmaf(fhi[j], v, acc_hi);
        }
        s_b[t]  = acc_lo;
        d1[r]   = acc_hi;
    }
    __syncthreads();   // s_b (lo1) complete; s_a (x) no longer needed past here

    // ---- Level 2 (dil=2): lo2 from s_b -> overwrite s_a ----
    // Safe without an extra barrier: after the sync above nobody reads s_a,
    // and lo2 computation only reads s_b.
    float lo2[SWT_EPT];
#pragma unroll
    for (int r = 0; r < SWT_EPT; ++r) {
        const int t = tid + r * SWT_NT;
        float acc_lo = 0.f;
#pragma unroll
        for (int j = 0; j < 8; ++j) {
            const float v = s_b[(t + 2 * (4 - j)) & SWT_TMASK];
            acc_lo = fmaf(flo[j], v, acc_lo);
        }
        lo2[r] = acc_lo;
    }
#pragma unroll
    for (int r = 0; r < SWT_EPT; ++r)
        s_a[tid + r * SWT_NT] = lo2[r];
    __syncthreads();   // s_a (lo2) complete before cross-thread dil=4 reads

    // ---- Final pass: d2 (s_b, dil=2), a3/d3 (s_a=lo2, dil=4), write float4 ----
    float4* out_row = out + (size_t)row * SWT_T;
#pragma unroll
    for (int r = 0; r < SWT_EPT; ++r) {
        const int t = tid + r * SWT_NT;

        float d2 = 0.f;
#pragma unroll
        for (int j = 0; j < 8; ++j)
            d2 = fmaf(fhi[j], s_b[(t + 2 * (4 - j)) & SWT_TMASK], d2);

        float a3 = 0.f, d3 = 0.f;
#pragma unroll
        for (int j = 0; j < 8; ++j) {
            const float v = s_a[(t + 4 * (4 - j)) & SWT_TMASK];
            a3 = fmaf(flo[j], v, a3);
            d3 = fmaf(fhi[j], v, d3);
        }

        out_row[t] = make_float4(a3, d3, d2, d1[r]);
    }
}

extern "C" void kernel_launch(void* const* d_in, const int* in_sizes, int n_in,
                              void* d_out, int out_size)
{
    const float* x      = (const float*)d_in[0];
    const float* dec_lo = (const float*)d_in[1];
    const float* dec_hi = (const float*)d_in[2];
    float4* out         = (float4*)d_out;

    const int rows = in_sizes[0] / SWT_T;   // 64*32 = 2048
    swt_db4_l3_kernel<<<rows, SWT_NT>>>(x, dec_lo, dec_hi, out);
}